// round 12
// baseline (speedup 1.0000x reference)
#include <cuda_runtime.h>
#include <cuda_fp16.h>
#include <cstdint>

#define N_NODES 100000
#define N_EDGES 1600000
#define D 128
#define NGRAPH 64
#define DOUT 16
#define LN_EPS 1e-5f
#define SCAN_B 1024
#define SCAN_NB ((N_NODES + SCAN_B - 1) / SCAN_B)   // 98

// ---------------- scratch (static device globals; no allocation) ----------------
__device__ __half g_Ah[N_NODES * D];     // GEMM output, dinv-prescaled, fp16
__device__ float  g_B[N_NODES * D];      // LN output (fp32) / GEMM input
__device__ int    g_cnti[N_NODES];
__device__ int    g_offs[N_NODES + 1];
__device__ int    g_cursor[N_NODES];
__device__ int    g_adj[N_EDGES];
__device__ int    g_bsum[SCAN_NB];
__device__ float  g_dinv[N_NODES];
__device__ float  g_pooled[NGRAPH * D];
__device__ float  g_gcnt[NGRAPH];

// ---------------- init ----------------
__global__ void k_init() {
    int i = blockIdx.x * blockDim.x + threadIdx.x;
    if (i < N_NODES) g_cnti[i] = 0;
    if (i < NGRAPH * D) g_pooled[i] = 0.0f;
    if (i < NGRAPH) g_gcnt[i] = 0.0f;
}

__global__ void k_count(const int* __restrict__ dst) {
    int i = blockIdx.x * blockDim.x + threadIdx.x;
    if (i < N_EDGES) atomicAdd(&g_cnti[dst[i]], 1);
}

__global__ void k_dinv() {
    int i = blockIdx.x * blockDim.x + threadIdx.x;
    if (i < N_NODES) g_dinv[i] = rsqrtf((float)(g_cnti[i] + 1));  // +1 self-loop
}

// ---------------- prefix scan ----------------
__global__ void k_scan1() {
    __shared__ int sh[SCAN_B];
    int i = blockIdx.x * SCAN_B + threadIdx.x;
    int v = (i < N_NODES) ? g_cnti[i] : 0;
    sh[threadIdx.x] = v;
    __syncthreads();
#pragma unroll
    for (int o = 1; o < SCAN_B; o <<= 1) {
        int t = (threadIdx.x >= o) ? sh[threadIdx.x - o] : 0;
        __syncthreads();
        sh[threadIdx.x] += t;
        __syncthreads();
    }
    if (i < N_NODES) g_offs[i + 1] = sh[threadIdx.x];
    if (threadIdx.x == SCAN_B - 1) g_bsum[blockIdx.x] = sh[SCAN_B - 1];
}

__global__ void k_scan2() {
    __shared__ int sh[128];
    int t = threadIdx.x;
    int v = (t < SCAN_NB) ? g_bsum[t] : 0;
    sh[t] = v;
    __syncthreads();
#pragma unroll
    for (int o = 1; o < 128; o <<= 1) {
        int u = (t >= o) ? sh[t - o] : 0;
        __syncthreads();
        sh[t] += u;
        __syncthreads();
    }
    if (t < SCAN_NB) g_bsum[t] = sh[t] - v;   // exclusive
}

__global__ void k_scan3() {
    int i = blockIdx.x * SCAN_B + threadIdx.x;
    if (i < N_NODES) {
        int incl = g_offs[i + 1] + g_bsum[blockIdx.x];
        g_offs[i + 1] = incl;
        if (i + 1 < N_NODES) g_cursor[i + 1] = incl;
    }
    if (i == 0) { g_offs[0] = 0; g_cursor[0] = 0; }
}

__global__ void k_fill(const int* __restrict__ src, const int* __restrict__ dst) {
    int e = blockIdx.x * blockDim.x + threadIdx.x;
    if (e < N_EDGES) {
        int d = dst[e];
        int pos = atomicAdd(&g_cursor[d], 1);
        g_adj[pos] = src[e];
    }
}

// ---------------- TF32 tensor-core GEMM, dinv-prescaled fp16 epilogue ----------------
#define AS_STRIDE 36
#define WS_STRIDE 132

__device__ __forceinline__ uint32_t f2tf32(float f) {
    uint32_t u;
    asm("cvt.rna.tf32.f32 %0, %1;" : "=r"(u) : "f"(f));
    return u;
}

__global__ void __launch_bounds__(256) k_gemm(const float* __restrict__ A,
                                              const float* __restrict__ W,
                                              __half* __restrict__ Ch) {
    __shared__ uint32_t As[128 * AS_STRIDE];
    __shared__ uint32_t Ws[32 * WS_STRIDE];
    int tid = threadIdx.x;
    int lane = tid & 31;
    int w = tid >> 5;
    int warpM = (w >> 1) * 32;
    int warpN = (w & 1) * 64;
    int g = lane >> 2;
    int t = lane & 3;
    int rowBase = blockIdx.x * 128;

    float c[2][8][4];
#pragma unroll
    for (int mi = 0; mi < 2; mi++)
#pragma unroll
        for (int nt = 0; nt < 8; nt++)
#pragma unroll
            for (int q = 0; q < 4; q++) c[mi][nt][q] = 0.f;

    for (int k0 = 0; k0 < 128; k0 += 32) {
#pragma unroll
        for (int i = 0; i < 4; i++) {
            int idx = tid + i * 256;
            int r = idx >> 3;
            int c4 = idx & 7;
            int grow = rowBase + r;
            float4 v = make_float4(0.f, 0.f, 0.f, 0.f);
            if (grow < N_NODES)
                v = *reinterpret_cast<const float4*>(&A[grow * D + k0 + c4 * 4]);
            uint32_t* p = &As[r * AS_STRIDE + c4 * 4];
            p[0] = f2tf32(v.x); p[1] = f2tf32(v.y);
            p[2] = f2tf32(v.z); p[3] = f2tf32(v.w);
        }
#pragma unroll
        for (int i = 0; i < 4; i++) {
            int idx = tid + i * 256;
            int r = idx >> 5;
            int c4 = idx & 31;
            float4 v = *reinterpret_cast<const float4*>(&W[(k0 + r) * D + c4 * 4]);
            uint32_t* p = &Ws[r * WS_STRIDE + c4 * 4];
            p[0] = f2tf32(v.x); p[1] = f2tf32(v.y);
            p[2] = f2tf32(v.z); p[3] = f2tf32(v.w);
        }
        __syncthreads();

#pragma unroll
        for (int kk = 0; kk < 4; kk++) {
            int kb = kk * 8;
            uint32_t af[2][4];
#pragma unroll
            for (int mi = 0; mi < 2; mi++) {
                int r = warpM + mi * 16;
                af[mi][0] = As[(r + g)     * AS_STRIDE + kb + t];
                af[mi][1] = As[(r + g + 8) * AS_STRIDE + kb + t];
                af[mi][2] = As[(r + g)     * AS_STRIDE + kb + t + 4];
                af[mi][3] = As[(r + g + 8) * AS_STRIDE + kb + t + 4];
            }
#pragma unroll
            for (int nt = 0; nt < 8; nt++) {
                int nb = warpN + nt * 8;
                uint32_t b0 = Ws[(kb + t)     * WS_STRIDE + nb + g];
                uint32_t b1 = Ws[(kb + t + 4) * WS_STRIDE + nb + g];
#pragma unroll
                for (int mi = 0; mi < 2; mi++) {
                    asm volatile(
                        "mma.sync.aligned.m16n8k8.row.col.f32.tf32.tf32.f32 "
                        "{%0,%1,%2,%3}, {%4,%5,%6,%7}, {%8,%9}, {%0,%1,%2,%3};"
                        : "+f"(c[mi][nt][0]), "+f"(c[mi][nt][1]),
                          "+f"(c[mi][nt][2]), "+f"(c[mi][nt][3])
                        : "r"(af[mi][0]), "r"(af[mi][1]), "r"(af[mi][2]), "r"(af[mi][3]),
                          "r"(b0), "r"(b1));
                }
            }
        }
        __syncthreads();
    }

    __half2* Ch2 = reinterpret_cast<__half2*>(Ch);
#pragma unroll
    for (int mi = 0; mi < 2; mi++) {
        int r0 = rowBase + warpM + mi * 16 + g;
        int r1 = r0 + 8;
        float d0 = (r0 < N_NODES) ? __ldg(&g_dinv[r0]) : 0.f;
        float d1 = (r1 < N_NODES) ? __ldg(&g_dinv[r1]) : 0.f;
#pragma unroll
        for (int nt = 0; nt < 8; nt++) {
            int colBase = warpN + nt * 8 + t * 2;
            if (r0 < N_NODES)
                Ch2[r0 * 64 + (colBase >> 1)] =
                    __floats2half2_rn(c[mi][nt][0] * d0, c[mi][nt][1] * d0);
            if (r1 < N_NODES)
                Ch2[r1 * 64 + (colBase >> 1)] =
                    __floats2half2_rn(c[mi][nt][2] * d1, c[mi][nt][3] * d1);
        }
    }
}

// ---------------- fused gather + self-loop + bias + LN + ReLU ----------------
// 16 lanes per node (2 nodes/warp); uint4 = 8 halfs per lane.
// ALL width-16 shuffles use the half-warp member mask (halves diverge!).
__device__ __forceinline__ void h8_to_f8(uint4 u, float* f) {
    float2 t;
    t = __half22float2(*reinterpret_cast<__half2*>(&u.x)); f[0] = t.x; f[1] = t.y;
    t = __half22float2(*reinterpret_cast<__half2*>(&u.y)); f[2] = t.x; f[3] = t.y;
    t = __half22float2(*reinterpret_cast<__half2*>(&u.z)); f[4] = t.x; f[5] = t.y;
    t = __half22float2(*reinterpret_cast<__half2*>(&u.w)); f[6] = t.x; f[7] = t.y;
}

__global__ void __launch_bounds__(256) k_gather(const __half* __restrict__ h,
                                                const float* __restrict__ bias,
                                                const float* __restrict__ lng,
                                                const float* __restrict__ lnb,
                                                float* __restrict__ out) {
    int node = blockIdx.x * 16 + (threadIdx.x >> 4);
    if (node >= N_NODES) return;
    int lane = threadIdx.x & 15;
    unsigned hm = 0xFFFFu << (threadIdx.x & 16);   // member mask of this half-warp
    float di = g_dinv[node];
    const uint4* __restrict__ hu = reinterpret_cast<const uint4*>(h);  // 8 halfs/elem
    int base = node * 16 + lane;

    float a0[8], a1[8];
    {
        uint4 su = __ldg(&hu[base]);      // self term (pre-scaled by dinv)
        h8_to_f8(su, a0);
#pragma unroll
        for (int q = 0; q < 8; q++) a1[q] = 0.f;
    }

    int beg = __ldg(&g_offs[node]);
    int end = __ldg(&g_offs[node + 1]);
    for (int j0 = beg; j0 < end; j0 += 16) {
        int rem = end - j0;
        int n = rem < 16 ? rem : 16;
        int myidx = 0;
        if (lane < n) myidx = __ldg(&g_adj[j0 + lane]);
        int jj = 0;
#pragma unroll 4
        for (; jj + 2 <= n; jj += 2) {
            int s0 = __shfl_sync(hm, myidx, jj, 16);
            int s1 = __shfl_sync(hm, myidx, jj + 1, 16);
            uint4 u0 = __ldg(&hu[s0 * 16 + lane]);
            uint4 u1 = __ldg(&hu[s1 * 16 + lane]);
            float f0[8], f1[8];
            h8_to_f8(u0, f0);
            h8_to_f8(u1, f1);
#pragma unroll
            for (int q = 0; q < 8; q++) { a0[q] += f0[q]; a1[q] += f1[q]; }
        }
        if (jj < n) {
            int s0 = __shfl_sync(hm, myidx, jj, 16);
            uint4 u0 = __ldg(&hu[s0 * 16 + lane]);
            float f0[8];
            h8_to_f8(u0, f0);
#pragma unroll
            for (int q = 0; q < 8; q++) a0[q] += f0[q];
        }
    }

    // bias + dinv scale
    const float4* b4p = reinterpret_cast<const float4*>(bias);
    float4 bA = __ldg(&b4p[lane * 2]);
    float4 bB = __ldg(&b4p[lane * 2 + 1]);
    float ax[8];
    ax[0] = (a0[0] + a1[0]) * di + bA.x;
    ax[1] = (a0[1] + a1[1]) * di + bA.y;
    ax[2] = (a0[2] + a1[2]) * di + bA.z;
    ax[3] = (a0[3] + a1[3]) * di + bA.w;
    ax[4] = (a0[4] + a1[4]) * di + bB.x;
    ax[5] = (a0[5] + a1[5]) * di + bB.y;
    ax[6] = (a0[6] + a1[6]) * di + bB.z;
    ax[7] = (a0[7] + a1[7]) * di + bB.w;

    // LayerNorm over 128 = 8 local + 16-lane reduce (half-warp mask)
    float s = 0.f;
#pragma unroll
    for (int q = 0; q < 8; q++) s += ax[q];
#pragma unroll
    for (int o = 8; o > 0; o >>= 1) s += __shfl_xor_sync(hm, s, o, 16);
    float mu = s * (1.0f / D);

    float dv[8];
    float sq = 0.f;
#pragma unroll
    for (int q = 0; q < 8; q++) { dv[q] = ax[q] - mu; sq += dv[q] * dv[q]; }
#pragma unroll
    for (int o = 8; o > 0; o >>= 1) sq += __shfl_xor_sync(hm, sq, o, 16);
    float rs = rsqrtf(sq * (1.0f / D) + LN_EPS);

    const float4* g4p = reinterpret_cast<const float4*>(lng);
    const float4* p4p = reinterpret_cast<const float4*>(lnb);
    float4 gA = __ldg(&g4p[lane * 2]);
    float4 gB = __ldg(&g4p[lane * 2 + 1]);
    float4 pA = __ldg(&p4p[lane * 2]);
    float4 pB = __ldg(&p4p[lane * 2 + 1]);

    float4 oA, oB;
    oA.x = fmaxf(dv[0] * rs * gA.x + pA.x, 0.f);
    oA.y = fmaxf(dv[1] * rs * gA.y + pA.y, 0.f);
    oA.z = fmaxf(dv[2] * rs * gA.z + pA.z, 0.f);
    oA.w = fmaxf(dv[3] * rs * gA.w + pA.w, 0.f);
    oB.x = fmaxf(dv[4] * rs * gB.x + pB.x, 0.f);
    oB.y = fmaxf(dv[5] * rs * gB.y + pB.y, 0.f);
    oB.z = fmaxf(dv[6] * rs * gB.z + pB.z, 0.f);
    oB.w = fmaxf(dv[7] * rs * gB.w + pB.w, 0.f);
    float4* o4p = reinterpret_cast<float4*>(out);
    o4p[node * 32 + lane * 2] = oA;
    o4p[node * 32 + lane * 2 + 1] = oB;
}

// ---------------- graph mean pool (batch sorted; node-count fused in) ----------------
#define POOL_CHUNK 128
__global__ void __launch_bounds__(128) k_pool(const float* __restrict__ h,
                                              const int* __restrict__ batch) {
    int f = threadIdx.x;
    int start = blockIdx.x * POOL_CHUNK;
    if (start >= N_NODES) return;
    int end = min(start + POOL_CHUNK, N_NODES);
    float sum = 0.f;
    int cnt = 0;
    int cur = __ldg(&batch[start]);
    for (int n = start; n < end; n++) {
        int gg = __ldg(&batch[n]);
        if (gg != cur) {
            atomicAdd(&g_pooled[cur * D + f], sum);
            if (f == 0) atomicAdd(&g_gcnt[cur], (float)cnt);
            sum = 0.f;
            cnt = 0;
            cur = gg;
        }
        sum += h[n * D + f];
        cnt++;
    }
    atomicAdd(&g_pooled[cur * D + f], sum);
    if (f == 0) atomicAdd(&g_gcnt[cur], (float)cnt);
}

// ---------------- head ----------------
__global__ void __launch_bounds__(1024) k_final(const float* __restrict__ lw,
                                                const float* __restrict__ lb,
                                                float* __restrict__ out) {
    int t = threadIdx.x;
    int g = t >> 4;
    int o = t & 15;
    float acc = 0.f;
#pragma unroll 8
    for (int f = 0; f < D; f++) acc += g_pooled[g * D + f] * __ldg(&lw[f * DOUT + o]);
    out[t] = acc / fmaxf(g_gcnt[g], 1.0f) + __ldg(&lb[o]);
}

// ---------------- launch (round-8 fork-join: CSR build overlaps GEMM1) ----------------
extern "C" void kernel_launch(void* const* d_in, const int* in_sizes, int n_in,
                              void* d_out, int out_size) {
    const float* x     = (const float*)d_in[0];
    const int*   ei    = (const int*)d_in[1];
    const int*   src   = ei;
    const int*   dst   = ei + N_EDGES;
    const int*   batch = (const int*)d_in[2];
    const float* W1    = (const float*)d_in[3];
    const float* b1    = (const float*)d_in[4];
    const float* W2    = (const float*)d_in[5];
    const float* b2    = (const float*)d_in[6];
    const float* lng   = (const float*)d_in[7];
    const float* lnb   = (const float*)d_in[8];
    const float* lw    = (const float*)d_in[9];
    const float* lbias = (const float*)d_in[10];
    float* out = (float*)d_out;

    __half* pAh = nullptr;
    float*  pB  = nullptr;
    cudaGetSymbolAddress((void**)&pAh, g_Ah);
    cudaGetSymbolAddress((void**)&pB, g_B);

    static cudaStream_t s_side = nullptr;
    static cudaEvent_t  s_evFork = nullptr, s_evJoin = nullptr;
    if (!s_side) {
        cudaStreamCreateWithFlags(&s_side, cudaStreamNonBlocking);
        cudaEventCreateWithFlags(&s_evFork, cudaEventDisableTiming);
        cudaEventCreateWithFlags(&s_evJoin, cudaEventDisableTiming);
    }
    cudaStream_t s0 = 0;

    const int T = 256;
    // prologue: counts + dinv
    k_init<<<(N_NODES + T - 1) / T, T, 0, s0>>>();
    k_count<<<(N_EDGES + T - 1) / T, T, 0, s0>>>(dst);
    k_dinv<<<(N_NODES + T - 1) / T, T, 0, s0>>>();

    // fork: side stream builds CSR while main stream runs GEMM1
    cudaEventRecord(s_evFork, s0);
    cudaStreamWaitEvent(s_side, s_evFork, 0);
    k_scan1<<<SCAN_NB, SCAN_B, 0, s_side>>>();
    k_scan2<<<1, 128, 0, s_side>>>();
    k_scan3<<<SCAN_NB, SCAN_B, 0, s_side>>>();
    k_fill<<<(N_EDGES + T - 1) / T, T, 0, s_side>>>(src, dst);
    cudaEventRecord(s_evJoin, s_side);

    k_gemm<<<(N_NODES + 127) / 128, 256, 0, s0>>>(x, W1, pAh);

    // join: gather1 needs both GEMM1 output and the CSR
    cudaStreamWaitEvent(s0, s_evJoin, 0);
    k_gather<<<(N_NODES + 15) / 16, 256, 0, s0>>>(pAh, b1, lng, lnb, pB);

    // layer 2
    k_gemm<<<(N_NODES + 127) / 128, 256, 0, s0>>>(pB, W2, pAh);
    k_gather<<<(N_NODES + 15) / 16, 256, 0, s0>>>(pAh, b2, lng, lnb, pB);

    // pool + head
    k_pool<<<(N_NODES + POOL_CHUNK - 1) / POOL_CHUNK, 128, 0, s0>>>(pB, batch);
    k_final<<<1, 1024, 0, s0>>>(lw, lbias, out);
}

// round 13
// speedup vs baseline: 1.1625x; 1.1625x over previous
#include <cuda_runtime.h>
#include <cuda_fp16.h>
#include <cstdint>

#define N_NODES 100000
#define N_EDGES 1600000
#define D 128
#define NGRAPH 64
#define DOUT 16
#define LN_EPS 1e-5f
#define SCAN_B 1024
#define SCAN_NB ((N_NODES + SCAN_B - 1) / SCAN_B)   // 98

// ---------------- scratch (static device globals; no allocation) ----------------
__device__ __half g_Ah[N_NODES * D];     // GEMM output, dinv-prescaled, fp16
__device__ float  g_B[N_NODES * D];      // reused: fp16 LN1 output lives here
__device__ int    g_cnti[N_NODES];
__device__ int    g_offs[N_NODES + 1];
__device__ int    g_cursor[N_NODES];
__device__ int    g_adj[N_EDGES];
__device__ int    g_bsum[SCAN_NB];
__device__ float  g_dinv[N_NODES];
__device__ float  g_pooled[NGRAPH * D];
__device__ float  g_gcnt[NGRAPH];

// ---------------- init ----------------
__global__ void k_init() {
    int i = blockIdx.x * blockDim.x + threadIdx.x;
    if (i < N_NODES) g_cnti[i] = 0;
    if (i < NGRAPH * D) g_pooled[i] = 0.0f;
    if (i < NGRAPH) g_gcnt[i] = 0.0f;
}

__global__ void k_count(const int* __restrict__ dst) {
    int i = blockIdx.x * blockDim.x + threadIdx.x;
    if (i < N_EDGES) atomicAdd(&g_cnti[dst[i]], 1);
}

__global__ void k_dinv() {
    int i = blockIdx.x * blockDim.x + threadIdx.x;
    if (i < N_NODES) g_dinv[i] = rsqrtf((float)(g_cnti[i] + 1));  // +1 self-loop
}

// ---------------- prefix scan ----------------
__global__ void k_scan1() {
    __shared__ int sh[SCAN_B];
    int i = blockIdx.x * SCAN_B + threadIdx.x;
    int v = (i < N_NODES) ? g_cnti[i] : 0;
    sh[threadIdx.x] = v;
    __syncthreads();
#pragma unroll
    for (int o = 1; o < SCAN_B; o <<= 1) {
        int t = (threadIdx.x >= o) ? sh[threadIdx.x - o] : 0;
        __syncthreads();
        sh[threadIdx.x] += t;
        __syncthreads();
    }
    if (i < N_NODES) g_offs[i + 1] = sh[threadIdx.x];
    if (threadIdx.x == SCAN_B - 1) g_bsum[blockIdx.x] = sh[SCAN_B - 1];
}

__global__ void k_scan2() {
    __shared__ int sh[128];
    int t = threadIdx.x;
    int v = (t < SCAN_NB) ? g_bsum[t] : 0;
    sh[t] = v;
    __syncthreads();
#pragma unroll
    for (int o = 1; o < 128; o <<= 1) {
        int u = (t >= o) ? sh[t - o] : 0;
        __syncthreads();
        sh[t] += u;
        __syncthreads();
    }
    if (t < SCAN_NB) g_bsum[t] = sh[t] - v;   // exclusive
}

__global__ void k_scan3() {
    int i = blockIdx.x * SCAN_B + threadIdx.x;
    if (i < N_NODES) {
        int incl = g_offs[i + 1] + g_bsum[blockIdx.x];
        g_offs[i + 1] = incl;
        if (i + 1 < N_NODES) g_cursor[i + 1] = incl;
    }
    if (i == 0) { g_offs[0] = 0; g_cursor[0] = 0; }
}

__global__ void k_fill(const int* __restrict__ src, const int* __restrict__ dst) {
    int e = blockIdx.x * blockDim.x + threadIdx.x;
    if (e < N_EDGES) {
        int d = dst[e];
        int pos = atomicAdd(&g_cursor[d], 1);
        g_adj[pos] = src[e];
    }
}

// ---------------- TF32 tensor-core GEMM core (shared by fp32/fp16 A) ----------------
#define AS_STRIDE 36
#define WS_STRIDE 132

__device__ __forceinline__ uint32_t f2tf32(float f) {
    uint32_t u;
    asm("cvt.rna.tf32.f32 %0, %1;" : "=r"(u) : "f"(f));
    return u;
}

__device__ __forceinline__ void gemm_core_and_store(
    uint32_t* As, uint32_t* Ws, const float* W, __half* Ch,
    int tid, int rowBase, int k0_is_loop /*unused*/) {}

__global__ void __launch_bounds__(256) k_gemm(const float* __restrict__ A,
                                              const float* __restrict__ W,
                                              __half* __restrict__ Ch) {
    __shared__ uint32_t As[128 * AS_STRIDE];
    __shared__ uint32_t Ws[32 * WS_STRIDE];
    int tid = threadIdx.x;
    int lane = tid & 31;
    int w = tid >> 5;
    int warpM = (w >> 1) * 32;
    int warpN = (w & 1) * 64;
    int g = lane >> 2;
    int t = lane & 3;
    int rowBase = blockIdx.x * 128;

    float c[2][8][4];
#pragma unroll
    for (int mi = 0; mi < 2; mi++)
#pragma unroll
        for (int nt = 0; nt < 8; nt++)
#pragma unroll
            for (int q = 0; q < 4; q++) c[mi][nt][q] = 0.f;

    for (int k0 = 0; k0 < 128; k0 += 32) {
#pragma unroll
        for (int i = 0; i < 4; i++) {
            int idx = tid + i * 256;
            int r = idx >> 3;
            int c4 = idx & 7;
            int grow = rowBase + r;
            float4 v = make_float4(0.f, 0.f, 0.f, 0.f);
            if (grow < N_NODES)
                v = *reinterpret_cast<const float4*>(&A[grow * D + k0 + c4 * 4]);
            uint32_t* p = &As[r * AS_STRIDE + c4 * 4];
            p[0] = f2tf32(v.x); p[1] = f2tf32(v.y);
            p[2] = f2tf32(v.z); p[3] = f2tf32(v.w);
        }
#pragma unroll
        for (int i = 0; i < 4; i++) {
            int idx = tid + i * 256;
            int r = idx >> 5;
            int c4 = idx & 31;
            float4 v = *reinterpret_cast<const float4*>(&W[(k0 + r) * D + c4 * 4]);
            uint32_t* p = &Ws[r * WS_STRIDE + c4 * 4];
            p[0] = f2tf32(v.x); p[1] = f2tf32(v.y);
            p[2] = f2tf32(v.z); p[3] = f2tf32(v.w);
        }
        __syncthreads();

#pragma unroll
        for (int kk = 0; kk < 4; kk++) {
            int kb = kk * 8;
            uint32_t af[2][4];
#pragma unroll
            for (int mi = 0; mi < 2; mi++) {
                int r = warpM + mi * 16;
                af[mi][0] = As[(r + g)     * AS_STRIDE + kb + t];
                af[mi][1] = As[(r + g + 8) * AS_STRIDE + kb + t];
                af[mi][2] = As[(r + g)     * AS_STRIDE + kb + t + 4];
                af[mi][3] = As[(r + g + 8) * AS_STRIDE + kb + t + 4];
            }
#pragma unroll
            for (int nt = 0; nt < 8; nt++) {
                int nb = warpN + nt * 8;
                uint32_t b0 = Ws[(kb + t)     * WS_STRIDE + nb + g];
                uint32_t b1 = Ws[(kb + t + 4) * WS_STRIDE + nb + g];
#pragma unroll
                for (int mi = 0; mi < 2; mi++) {
                    asm volatile(
                        "mma.sync.aligned.m16n8k8.row.col.f32.tf32.tf32.f32 "
                        "{%0,%1,%2,%3}, {%4,%5,%6,%7}, {%8,%9}, {%0,%1,%2,%3};"
                        : "+f"(c[mi][nt][0]), "+f"(c[mi][nt][1]),
                          "+f"(c[mi][nt][2]), "+f"(c[mi][nt][3])
                        : "r"(af[mi][0]), "r"(af[mi][1]), "r"(af[mi][2]), "r"(af[mi][3]),
                          "r"(b0), "r"(b1));
                }
            }
        }
        __syncthreads();
    }

    __half2* Ch2 = reinterpret_cast<__half2*>(Ch);
#pragma unroll
    for (int mi = 0; mi < 2; mi++) {
        int r0 = rowBase + warpM + mi * 16 + g;
        int r1 = r0 + 8;
        float d0 = (r0 < N_NODES) ? __ldg(&g_dinv[r0]) : 0.f;
        float d1 = (r1 < N_NODES) ? __ldg(&g_dinv[r1]) : 0.f;
#pragma unroll
        for (int nt = 0; nt < 8; nt++) {
            int colBase = warpN + nt * 8 + t * 2;
            if (r0 < N_NODES)
                Ch2[r0 * 64 + (colBase >> 1)] =
                    __floats2half2_rn(c[mi][nt][0] * d0, c[mi][nt][1] * d0);
            if (r1 < N_NODES)
                Ch2[r1 * 64 + (colBase >> 1)] =
                    __floats2half2_rn(c[mi][nt][2] * d1, c[mi][nt][3] * d1);
        }
    }
}

// Same GEMM but A is fp16 (LN1 output)
__global__ void __launch_bounds__(256) k_gemmh(const __half* __restrict__ A,
                                               const float* __restrict__ W,
                                               __half* __restrict__ Ch) {
    __shared__ uint32_t As[128 * AS_STRIDE];
    __shared__ uint32_t Ws[32 * WS_STRIDE];
    int tid = threadIdx.x;
    int lane = tid & 31;
    int w = tid >> 5;
    int warpM = (w >> 1) * 32;
    int warpN = (w & 1) * 64;
    int g = lane >> 2;
    int t = lane & 3;
    int rowBase = blockIdx.x * 128;

    float c[2][8][4];
#pragma unroll
    for (int mi = 0; mi < 2; mi++)
#pragma unroll
        for (int nt = 0; nt < 8; nt++)
#pragma unroll
            for (int q = 0; q < 4; q++) c[mi][nt][q] = 0.f;

    for (int k0 = 0; k0 < 128; k0 += 32) {
#pragma unroll
        for (int i = 0; i < 4; i++) {
            int idx = tid + i * 256;
            int r = idx >> 3;
            int c4 = idx & 7;
            int grow = rowBase + r;
            uint2 v = make_uint2(0u, 0u);
            if (grow < N_NODES)
                v = *reinterpret_cast<const uint2*>(&A[grow * D + k0 + c4 * 4]);
            float2 f0 = __half22float2(*reinterpret_cast<__half2*>(&v.x));
            float2 f1 = __half22float2(*reinterpret_cast<__half2*>(&v.y));
            uint32_t* p = &As[r * AS_STRIDE + c4 * 4];
            p[0] = f2tf32(f0.x); p[1] = f2tf32(f0.y);
            p[2] = f2tf32(f1.x); p[3] = f2tf32(f1.y);
        }
#pragma unroll
        for (int i = 0; i < 4; i++) {
            int idx = tid + i * 256;
            int r = idx >> 5;
            int c4 = idx & 31;
            float4 v = *reinterpret_cast<const float4*>(&W[(k0 + r) * D + c4 * 4]);
            uint32_t* p = &Ws[r * WS_STRIDE + c4 * 4];
            p[0] = f2tf32(v.x); p[1] = f2tf32(v.y);
            p[2] = f2tf32(v.z); p[3] = f2tf32(v.w);
        }
        __syncthreads();

#pragma unroll
        for (int kk = 0; kk < 4; kk++) {
            int kb = kk * 8;
            uint32_t af[2][4];
#pragma unroll
            for (int mi = 0; mi < 2; mi++) {
                int r = warpM + mi * 16;
                af[mi][0] = As[(r + g)     * AS_STRIDE + kb + t];
                af[mi][1] = As[(r + g + 8) * AS_STRIDE + kb + t];
                af[mi][2] = As[(r + g)     * AS_STRIDE + kb + t + 4];
                af[mi][3] = As[(r + g + 8) * AS_STRIDE + kb + t + 4];
            }
#pragma unroll
            for (int nt = 0; nt < 8; nt++) {
                int nb = warpN + nt * 8;
                uint32_t b0 = Ws[(kb + t)     * WS_STRIDE + nb + g];
                uint32_t b1 = Ws[(kb + t + 4) * WS_STRIDE + nb + g];
#pragma unroll
                for (int mi = 0; mi < 2; mi++) {
                    asm volatile(
                        "mma.sync.aligned.m16n8k8.row.col.f32.tf32.tf32.f32 "
                        "{%0,%1,%2,%3}, {%4,%5,%6,%7}, {%8,%9}, {%0,%1,%2,%3};"
                        : "+f"(c[mi][nt][0]), "+f"(c[mi][nt][1]),
                          "+f"(c[mi][nt][2]), "+f"(c[mi][nt][3])
                        : "r"(af[mi][0]), "r"(af[mi][1]), "r"(af[mi][2]), "r"(af[mi][3]),
                          "r"(b0), "r"(b1));
                }
            }
        }
        __syncthreads();
    }

    __half2* Ch2 = reinterpret_cast<__half2*>(Ch);
#pragma unroll
    for (int mi = 0; mi < 2; mi++) {
        int r0 = rowBase + warpM + mi * 16 + g;
        int r1 = r0 + 8;
        float d0 = (r0 < N_NODES) ? __ldg(&g_dinv[r0]) : 0.f;
        float d1 = (r1 < N_NODES) ? __ldg(&g_dinv[r1]) : 0.f;
#pragma unroll
        for (int nt = 0; nt < 8; nt++) {
            int colBase = warpN + nt * 8 + t * 2;
            if (r0 < N_NODES)
                Ch2[r0 * 64 + (colBase >> 1)] =
                    __floats2half2_rn(c[mi][nt][0] * d0, c[mi][nt][1] * d0);
            if (r1 < N_NODES)
                Ch2[r1 * 64 + (colBase >> 1)] =
                    __floats2half2_rn(c[mi][nt][2] * d1, c[mi][nt][3] * d1);
        }
    }
}

// ---------------- gather body (round-8 proven 32-lane version) ----------------
// Computes the LN'd + ReLU'd row for `node`, result in o4 (4 floats per lane).
__device__ __forceinline__ float4 gather_ln_row(const __half* __restrict__ h,
                                                const float* __restrict__ bias,
                                                const float* __restrict__ lng,
                                                const float* __restrict__ lnb,
                                                int node, int lane) {
    float di = g_dinv[node];
    const uint2* __restrict__ hu = reinterpret_cast<const uint2*>(h);
    int base = node * 32 + lane;

    uint2 su = __ldg(&hu[base]);
    float2 sf0 = __half22float2(*reinterpret_cast<__half2*>(&su.x));
    float2 sf1 = __half22float2(*reinterpret_cast<__half2*>(&su.y));
    float a0x = sf0.x, a0y = sf0.y, a0z = sf1.x, a0w = sf1.y;
    float a1x = 0.f, a1y = 0.f, a1z = 0.f, a1w = 0.f;

    int beg = __ldg(&g_offs[node]);
    int end = __ldg(&g_offs[node + 1]);
    for (int j0 = beg; j0 < end; j0 += 32) {
        int rem = end - j0;
        int n = rem < 32 ? rem : 32;
        int myidx = 0;
        if (lane < n) myidx = __ldg(&g_adj[j0 + lane]);
        int jj = 0;
#pragma unroll 4
        for (; jj + 2 <= n; jj += 2) {
            int s0 = __shfl_sync(0xFFFFFFFFu, myidx, jj);
            int s1 = __shfl_sync(0xFFFFFFFFu, myidx, jj + 1);
            uint2 u0 = __ldg(&hu[s0 * 32 + lane]);
            uint2 u1 = __ldg(&hu[s1 * 32 + lane]);
            float2 f00 = __half22float2(*reinterpret_cast<__half2*>(&u0.x));
            float2 f01 = __half22float2(*reinterpret_cast<__half2*>(&u0.y));
            float2 f10 = __half22float2(*reinterpret_cast<__half2*>(&u1.x));
            float2 f11 = __half22float2(*reinterpret_cast<__half2*>(&u1.y));
            a0x += f00.x; a1x += f10.x;
            a0y += f00.y; a1y += f10.y;
            a0z += f01.x; a1z += f11.x;
            a0w += f01.y; a1w += f11.y;
        }
        if (jj < n) {
            int s0 = __shfl_sync(0xFFFFFFFFu, myidx, jj);
            uint2 u0 = __ldg(&hu[s0 * 32 + lane]);
            float2 f00 = __half22float2(*reinterpret_cast<__half2*>(&u0.x));
            float2 f01 = __half22float2(*reinterpret_cast<__half2*>(&u0.y));
            a0x += f00.x; a0y += f00.y; a0z += f01.x; a0w += f01.y;
        }
    }

    float4 b4 = __ldg(&reinterpret_cast<const float4*>(bias)[lane]);
    float ax = (a0x + a1x) * di + b4.x;
    float ay = (a0y + a1y) * di + b4.y;
    float az = (a0z + a1z) * di + b4.z;
    float aw = (a0w + a1w) * di + b4.w;

    float s = ax + ay + az + aw;
#pragma unroll
    for (int o = 16; o > 0; o >>= 1) s += __shfl_xor_sync(0xFFFFFFFFu, s, o);
    float mu = s * (1.0f / D);
    float dx = ax - mu, dy = ay - mu, dz = az - mu, dw = aw - mu;
    float sq = dx * dx + dy * dy + dz * dz + dw * dw;
#pragma unroll
    for (int o = 16; o > 0; o >>= 1) sq += __shfl_xor_sync(0xFFFFFFFFu, sq, o);
    float rs = rsqrtf(sq * (1.0f / D) + LN_EPS);

    float4 g4 = __ldg(&reinterpret_cast<const float4*>(lng)[lane]);
    float4 p4 = __ldg(&reinterpret_cast<const float4*>(lnb)[lane]);
    float4 o4;
    o4.x = fmaxf(dx * rs * g4.x + p4.x, 0.f);
    o4.y = fmaxf(dy * rs * g4.y + p4.y, 0.f);
    o4.z = fmaxf(dz * rs * g4.z + p4.z, 0.f);
    o4.w = fmaxf(dw * rs * g4.w + p4.w, 0.f);
    return o4;
}

// gather1: writes fp16 rows (consumed by k_gemmh)
__global__ void __launch_bounds__(256) k_gather1(const __half* __restrict__ h,
                                                 const float* __restrict__ bias,
                                                 const float* __restrict__ lng,
                                                 const float* __restrict__ lnb,
                                                 __half* __restrict__ outh) {
    int node = blockIdx.x * 8 + (threadIdx.x >> 5);
    if (node >= N_NODES) return;
    int lane = threadIdx.x & 31;
    float4 o4 = gather_ln_row(h, bias, lng, lnb, node, lane);
    __half2 h0 = __floats2half2_rn(o4.x, o4.y);
    __half2 h1 = __floats2half2_rn(o4.z, o4.w);
    uint2 wv;
    wv.x = *reinterpret_cast<uint32_t*>(&h0);
    wv.y = *reinterpret_cast<uint32_t*>(&h1);
    reinterpret_cast<uint2*>(outh)[node * 32 + lane] = wv;
}

// gather2: no feature output; accumulates directly into g_pooled/g_gcnt.
// Grid is exactly N_NODES/8 blocks (100000 = 12500*8) -> no tail, syncthreads safe.
__global__ void __launch_bounds__(256) k_gather2_pool(const __half* __restrict__ h,
                                                      const float* __restrict__ bias,
                                                      const float* __restrict__ lng,
                                                      const float* __restrict__ lnb,
                                                      const int* __restrict__ batch) {
    __shared__ float acc[D];
    __shared__ int scnt;
    int tid = threadIdx.x;
    int node = blockIdx.x * 8 + (tid >> 5);
    int lane = tid & 31;

    if (tid < D) acc[tid] = 0.f;
    if (tid == 0) scnt = 0;
    __syncthreads();

    float4 o4 = gather_ln_row(h, bias, lng, lnb, node, lane);

    int gFirst = __ldg(&batch[blockIdx.x * 8]);
    int gMine  = __ldg(&batch[node]);
    if (gMine == gFirst) {
        atomicAdd(&acc[lane * 4 + 0], o4.x);
        atomicAdd(&acc[lane * 4 + 1], o4.y);
        atomicAdd(&acc[lane * 4 + 2], o4.z);
        atomicAdd(&acc[lane * 4 + 3], o4.w);
        if (lane == 0) atomicAdd(&scnt, 1);
    } else {
        // rare: node belongs to a later graph than block leader
        atomicAdd(&g_pooled[gMine * D + lane * 4 + 0], o4.x);
        atomicAdd(&g_pooled[gMine * D + lane * 4 + 1], o4.y);
        atomicAdd(&g_pooled[gMine * D + lane * 4 + 2], o4.z);
        atomicAdd(&g_pooled[gMine * D + lane * 4 + 3], o4.w);
        if (lane == 0) atomicAdd(&g_gcnt[gMine], 1.0f);
    }
    __syncthreads();

    if (tid < D) atomicAdd(&g_pooled[gFirst * D + tid], acc[tid]);
    if (tid == 0) atomicAdd(&g_gcnt[gFirst], (float)scnt);
}

// ---------------- head ----------------
__global__ void __launch_bounds__(1024) k_final(const float* __restrict__ lw,
                                                const float* __restrict__ lb,
                                                float* __restrict__ out) {
    int t = threadIdx.x;
    int g = t >> 4;
    int o = t & 15;
    float acc = 0.f;
#pragma unroll 8
    for (int f = 0; f < D; f++) acc += g_pooled[g * D + f] * __ldg(&lw[f * DOUT + o]);
    out[t] = acc / fmaxf(g_gcnt[g], 1.0f) + __ldg(&lb[o]);
}

// ---------------- launch (round-8 fork-join: CSR build overlaps GEMM1) ----------------
extern "C" void kernel_launch(void* const* d_in, const int* in_sizes, int n_in,
                              void* d_out, int out_size) {
    const float* x     = (const float*)d_in[0];
    const int*   ei    = (const int*)d_in[1];
    const int*   src   = ei;
    const int*   dst   = ei + N_EDGES;
    const int*   batch = (const int*)d_in[2];
    const float* W1    = (const float*)d_in[3];
    const float* b1    = (const float*)d_in[4];
    const float* W2    = (const float*)d_in[5];
    const float* b2    = (const float*)d_in[6];
    const float* lng   = (const float*)d_in[7];
    const float* lnb   = (const float*)d_in[8];
    const float* lw    = (const float*)d_in[9];
    const float* lbias = (const float*)d_in[10];
    float* out = (float*)d_out;

    __half* pAh = nullptr;
    float*  pB  = nullptr;
    cudaGetSymbolAddress((void**)&pAh, g_Ah);
    cudaGetSymbolAddress((void**)&pB, g_B);
    __half* pBh = (__half*)pB;   // fp16 LN1 output aliases g_B

    static cudaStream_t s_side = nullptr;
    static cudaEvent_t  s_evFork = nullptr, s_evJoin = nullptr;
    if (!s_side) {
        cudaStreamCreateWithFlags(&s_side, cudaStreamNonBlocking);
        cudaEventCreateWithFlags(&s_evFork, cudaEventDisableTiming);
        cudaEventCreateWithFlags(&s_evJoin, cudaEventDisableTiming);
    }
    cudaStream_t s0 = 0;

    const int T = 256;
    // prologue: counts + dinv
    k_init<<<(N_NODES + T - 1) / T, T, 0, s0>>>();
    k_count<<<(N_EDGES + T - 1) / T, T, 0, s0>>>(dst);
    k_dinv<<<(N_NODES + T - 1) / T, T, 0, s0>>>();

    // fork: side stream builds CSR while main stream runs GEMM1
    cudaEventRecord(s_evFork, s0);
    cudaStreamWaitEvent(s_side, s_evFork, 0);
    k_scan1<<<SCAN_NB, SCAN_B, 0, s_side>>>();
    k_scan2<<<1, 128, 0, s_side>>>();
    k_scan3<<<SCAN_NB, SCAN_B, 0, s_side>>>();
    k_fill<<<(N_EDGES + T - 1) / T, T, 0, s_side>>>(src, dst);
    cudaEventRecord(s_evJoin, s_side);

    k_gemm<<<(N_NODES + 127) / 128, 256, 0, s0>>>(x, W1, pAh);

    // join: gather1 needs both GEMM1 output and the CSR
    cudaStreamWaitEvent(s0, s_evJoin, 0);
    k_gather1<<<(N_NODES + 7) / 8, 256, 0, s0>>>(pAh, b1, lng, lnb, pBh);

    // layer 2 (fp16 input GEMM)
    k_gemmh<<<(N_NODES + 127) / 128, 256, 0, s0>>>(pBh, W2, pAh);
    k_gather2_pool<<<(N_NODES + 7) / 8, 256, 0, s0>>>(pAh, b2, lng, lnb, batch);

    // head
    k_final<<<1, 1024, 0, s0>>>(lw, lbias, out);
}

// round 14
// speedup vs baseline: 1.1719x; 1.0081x over previous
#include <cuda_runtime.h>
#include <cuda_fp16.h>
#include <cstdint>

#define N_NODES 100000
#define N_EDGES 1600000
#define D 128
#define NGRAPH 64
#define DOUT 16
#define LN_EPS 1e-5f
#define SCAN_B 1024
#define SCAN_NB ((N_NODES + SCAN_B - 1) / SCAN_B)   // 98

// ---------------- scratch (static device globals; no allocation) ----------------
// NOTE: zero-init at module load; k_zero re-zeroes cnti/pooled/gcnt within every
// launch after their last consumers, so each call sees the same initial state.
__device__ __half g_Ah[N_NODES * D];     // GEMM output, dinv-prescaled, fp16
__device__ float  g_B[N_NODES * D];      // fp16 LN1 output lives here
__device__ int    g_cnti[N_NODES];
__device__ int    g_offs[N_NODES + 1];
__device__ int    g_cursor[N_NODES];
__device__ int    g_adj[N_EDGES];
__device__ int    g_bsum[SCAN_NB];
__device__ float  g_dinv[N_NODES];
__device__ float  g_pooled[NGRAPH * D];
__device__ float  g_gcnt[NGRAPH];

// ---------------- degree count ----------------
__global__ void k_count(const int* __restrict__ dst) {
    int i = blockIdx.x * blockDim.x + threadIdx.x;
    if (i < N_EDGES) atomicAdd(&g_cnti[dst[i]], 1);
}

// ---------------- prefix scan (dinv fused into scan1) ----------------
__global__ void k_scan1() {
    __shared__ int sh[SCAN_B];
    int i = blockIdx.x * SCAN_B + threadIdx.x;
    int v = (i < N_NODES) ? g_cnti[i] : 0;
    if (i < N_NODES) g_dinv[i] = rsqrtf((float)(v + 1));   // +1 self-loop
    sh[threadIdx.x] = v;
    __syncthreads();
#pragma unroll
    for (int o = 1; o < SCAN_B; o <<= 1) {
        int t = (threadIdx.x >= o) ? sh[threadIdx.x - o] : 0;
        __syncthreads();
        sh[threadIdx.x] += t;
        __syncthreads();
    }
    if (i < N_NODES) g_offs[i + 1] = sh[threadIdx.x];
    if (threadIdx.x == SCAN_B - 1) g_bsum[blockIdx.x] = sh[SCAN_B - 1];
}

__global__ void k_scan2() {
    __shared__ int sh[128];
    int t = threadIdx.x;
    int v = (t < SCAN_NB) ? g_bsum[t] : 0;
    sh[t] = v;
    __syncthreads();
#pragma unroll
    for (int o = 1; o < 128; o <<= 1) {
        int u = (t >= o) ? sh[t - o] : 0;
        __syncthreads();
        sh[t] += u;
        __syncthreads();
    }
    if (t < SCAN_NB) g_bsum[t] = sh[t] - v;   // exclusive
}

__global__ void k_scan3() {
    int i = blockIdx.x * SCAN_B + threadIdx.x;
    if (i < N_NODES) {
        int incl = g_offs[i + 1] + g_bsum[blockIdx.x];
        g_offs[i + 1] = incl;
        if (i + 1 < N_NODES) g_cursor[i + 1] = incl;
    }
    if (i == 0) { g_offs[0] = 0; g_cursor[0] = 0; }
}

__global__ void k_fill(const int* __restrict__ src, const int* __restrict__ dst) {
    int e = blockIdx.x * blockDim.x + threadIdx.x;
    if (e < N_EDGES) {
        int d = dst[e];
        int pos = atomicAdd(&g_cursor[d], 1);
        g_adj[pos] = src[e];
    }
}

// zero cnti/pooled/gcnt for the rest of this launch + the next call.
// Runs on the side stream after gemm1's epilogue (last cnti reader) and
// before the join (gather2_pool needs pooled/gcnt zeroed).
__global__ void k_zero() {
    int i = blockIdx.x * blockDim.x + threadIdx.x;
    if (i < N_NODES) g_cnti[i] = 0;
    if (i < NGRAPH * D) g_pooled[i] = 0.0f;
    if (i < NGRAPH) g_gcnt[i] = 0.0f;
}

// ---------------- TF32 tensor-core GEMM ----------------
#define AS_STRIDE 36
#define WS_STRIDE 132

__device__ __forceinline__ uint32_t f2tf32(float f) {
    uint32_t u;
    asm("cvt.rna.tf32.f32 %0, %1;" : "=r"(u) : "f"(f));
    return u;
}

// GEMM1: fp32 A; epilogue computes dinv from cnti (g_dinv not yet written).
__global__ void __launch_bounds__(256) k_gemm(const float* __restrict__ A,
                                              const float* __restrict__ W,
                                              __half* __restrict__ Ch) {
    __shared__ uint32_t As[128 * AS_STRIDE];
    __shared__ uint32_t Ws[32 * WS_STRIDE];
    int tid = threadIdx.x;
    int lane = tid & 31;
    int w = tid >> 5;
    int warpM = (w >> 1) * 32;
    int warpN = (w & 1) * 64;
    int g = lane >> 2;
    int t = lane & 3;
    int rowBase = blockIdx.x * 128;

    float c[2][8][4];
#pragma unroll
    for (int mi = 0; mi < 2; mi++)
#pragma unroll
        for (int nt = 0; nt < 8; nt++)
#pragma unroll
            for (int q = 0; q < 4; q++) c[mi][nt][q] = 0.f;

    for (int k0 = 0; k0 < 128; k0 += 32) {
#pragma unroll
        for (int i = 0; i < 4; i++) {
            int idx = tid + i * 256;
            int r = idx >> 3;
            int c4 = idx & 7;
            int grow = rowBase + r;
            float4 v = make_float4(0.f, 0.f, 0.f, 0.f);
            if (grow < N_NODES)
                v = *reinterpret_cast<const float4*>(&A[grow * D + k0 + c4 * 4]);
            uint32_t* p = &As[r * AS_STRIDE + c4 * 4];
            p[0] = f2tf32(v.x); p[1] = f2tf32(v.y);
            p[2] = f2tf32(v.z); p[3] = f2tf32(v.w);
        }
#pragma unroll
        for (int i = 0; i < 4; i++) {
            int idx = tid + i * 256;
            int r = idx >> 5;
            int c4 = idx & 31;
            float4 v = *reinterpret_cast<const float4*>(&W[(k0 + r) * D + c4 * 4]);
            uint32_t* p = &Ws[r * WS_STRIDE + c4 * 4];
            p[0] = f2tf32(v.x); p[1] = f2tf32(v.y);
            p[2] = f2tf32(v.z); p[3] = f2tf32(v.w);
        }
        __syncthreads();

#pragma unroll
        for (int kk = 0; kk < 4; kk++) {
            int kb = kk * 8;
            uint32_t af[2][4];
#pragma unroll
            for (int mi = 0; mi < 2; mi++) {
                int r = warpM + mi * 16;
                af[mi][0] = As[(r + g)     * AS_STRIDE + kb + t];
                af[mi][1] = As[(r + g + 8) * AS_STRIDE + kb + t];
                af[mi][2] = As[(r + g)     * AS_STRIDE + kb + t + 4];
                af[mi][3] = As[(r + g + 8) * AS_STRIDE + kb + t + 4];
            }
#pragma unroll
            for (int nt = 0; nt < 8; nt++) {
                int nb = warpN + nt * 8;
                uint32_t b0 = Ws[(kb + t)     * WS_STRIDE + nb + g];
                uint32_t b1 = Ws[(kb + t + 4) * WS_STRIDE + nb + g];
#pragma unroll
                for (int mi = 0; mi < 2; mi++) {
                    asm volatile(
                        "mma.sync.aligned.m16n8k8.row.col.f32.tf32.tf32.f32 "
                        "{%0,%1,%2,%3}, {%4,%5,%6,%7}, {%8,%9}, {%0,%1,%2,%3};"
                        : "+f"(c[mi][nt][0]), "+f"(c[mi][nt][1]),
                          "+f"(c[mi][nt][2]), "+f"(c[mi][nt][3])
                        : "r"(af[mi][0]), "r"(af[mi][1]), "r"(af[mi][2]), "r"(af[mi][3]),
                          "r"(b0), "r"(b1));
                }
            }
        }
        __syncthreads();
    }

    __half2* Ch2 = reinterpret_cast<__half2*>(Ch);
#pragma unroll
    for (int mi = 0; mi < 2; mi++) {
        int r0 = rowBase + warpM + mi * 16 + g;
        int r1 = r0 + 8;
        float d0 = (r0 < N_NODES) ? rsqrtf((float)(__ldg(&g_cnti[r0]) + 1)) : 0.f;
        float d1 = (r1 < N_NODES) ? rsqrtf((float)(__ldg(&g_cnti[r1]) + 1)) : 0.f;
#pragma unroll
        for (int nt = 0; nt < 8; nt++) {
            int colBase = warpN + nt * 8 + t * 2;
            if (r0 < N_NODES)
                Ch2[r0 * 64 + (colBase >> 1)] =
                    __floats2half2_rn(c[mi][nt][0] * d0, c[mi][nt][1] * d0);
            if (r1 < N_NODES)
                Ch2[r1 * 64 + (colBase >> 1)] =
                    __floats2half2_rn(c[mi][nt][2] * d1, c[mi][nt][3] * d1);
        }
    }
}

// GEMM2: fp16 A (LN1 output); epilogue uses g_dinv (ready after join).
__global__ void __launch_bounds__(256) k_gemmh(const __half* __restrict__ A,
                                               const float* __restrict__ W,
                                               __half* __restrict__ Ch) {
    __shared__ uint32_t As[128 * AS_STRIDE];
    __shared__ uint32_t Ws[32 * WS_STRIDE];
    int tid = threadIdx.x;
    int lane = tid & 31;
    int w = tid >> 5;
    int warpM = (w >> 1) * 32;
    int warpN = (w & 1) * 64;
    int g = lane >> 2;
    int t = lane & 3;
    int rowBase = blockIdx.x * 128;

    float c[2][8][4];
#pragma unroll
    for (int mi = 0; mi < 2; mi++)
#pragma unroll
        for (int nt = 0; nt < 8; nt++)
#pragma unroll
            for (int q = 0; q < 4; q++) c[mi][nt][q] = 0.f;

    for (int k0 = 0; k0 < 128; k0 += 32) {
#pragma unroll
        for (int i = 0; i < 4; i++) {
            int idx = tid + i * 256;
            int r = idx >> 3;
            int c4 = idx & 7;
            int grow = rowBase + r;
            uint2 v = make_uint2(0u, 0u);
            if (grow < N_NODES)
                v = *reinterpret_cast<const uint2*>(&A[grow * D + k0 + c4 * 4]);
            float2 f0 = __half22float2(*reinterpret_cast<__half2*>(&v.x));
            float2 f1 = __half22float2(*reinterpret_cast<__half2*>(&v.y));
            uint32_t* p = &As[r * AS_STRIDE + c4 * 4];
            p[0] = f2tf32(f0.x); p[1] = f2tf32(f0.y);
            p[2] = f2tf32(f1.x); p[3] = f2tf32(f1.y);
        }
#pragma unroll
        for (int i = 0; i < 4; i++) {
            int idx = tid + i * 256;
            int r = idx >> 5;
            int c4 = idx & 31;
            float4 v = *reinterpret_cast<const float4*>(&W[(k0 + r) * D + c4 * 4]);
            uint32_t* p = &Ws[r * WS_STRIDE + c4 * 4];
            p[0] = f2tf32(v.x); p[1] = f2tf32(v.y);
            p[2] = f2tf32(v.z); p[3] = f2tf32(v.w);
        }
        __syncthreads();

#pragma unroll
        for (int kk = 0; kk < 4; kk++) {
            int kb = kk * 8;
            uint32_t af[2][4];
#pragma unroll
            for (int mi = 0; mi < 2; mi++) {
                int r = warpM + mi * 16;
                af[mi][0] = As[(r + g)     * AS_STRIDE + kb + t];
                af[mi][1] = As[(r + g + 8) * AS_STRIDE + kb + t];
                af[mi][2] = As[(r + g)     * AS_STRIDE + kb + t + 4];
                af[mi][3] = As[(r + g + 8) * AS_STRIDE + kb + t + 4];
            }
#pragma unroll
            for (int nt = 0; nt < 8; nt++) {
                int nb = warpN + nt * 8;
                uint32_t b0 = Ws[(kb + t)     * WS_STRIDE + nb + g];
                uint32_t b1 = Ws[(kb + t + 4) * WS_STRIDE + nb + g];
#pragma unroll
                for (int mi = 0; mi < 2; mi++) {
                    asm volatile(
                        "mma.sync.aligned.m16n8k8.row.col.f32.tf32.tf32.f32 "
                        "{%0,%1,%2,%3}, {%4,%5,%6,%7}, {%8,%9}, {%0,%1,%2,%3};"
                        : "+f"(c[mi][nt][0]), "+f"(c[mi][nt][1]),
                          "+f"(c[mi][nt][2]), "+f"(c[mi][nt][3])
                        : "r"(af[mi][0]), "r"(af[mi][1]), "r"(af[mi][2]), "r"(af[mi][3]),
                          "r"(b0), "r"(b1));
                }
            }
        }
        __syncthreads();
    }

    __half2* Ch2 = reinterpret_cast<__half2*>(Ch);
#pragma unroll
    for (int mi = 0; mi < 2; mi++) {
        int r0 = rowBase + warpM + mi * 16 + g;
        int r1 = r0 + 8;
        float d0 = (r0 < N_NODES) ? __ldg(&g_dinv[r0]) : 0.f;
        float d1 = (r1 < N_NODES) ? __ldg(&g_dinv[r1]) : 0.f;
#pragma unroll
        for (int nt = 0; nt < 8; nt++) {
            int colBase = warpN + nt * 8 + t * 2;
            if (r0 < N_NODES)
                Ch2[r0 * 64 + (colBase >> 1)] =
                    __floats2half2_rn(c[mi][nt][0] * d0, c[mi][nt][1] * d0);
            if (r1 < N_NODES)
                Ch2[r1 * 64 + (colBase >> 1)] =
                    __floats2half2_rn(c[mi][nt][2] * d1, c[mi][nt][3] * d1);
        }
    }
}

// ---------------- gather body (proven 32-lane version) ----------------
__device__ __forceinline__ float4 gather_ln_row(const __half* __restrict__ h,
                                                const float* __restrict__ bias,
                                                const float* __restrict__ lng,
                                                const float* __restrict__ lnb,
                                                int node, int lane) {
    float di = g_dinv[node];
    const uint2* __restrict__ hu = reinterpret_cast<const uint2*>(h);
    int base = node * 32 + lane;

    uint2 su = __ldg(&hu[base]);
    float2 sf0 = __half22float2(*reinterpret_cast<__half2*>(&su.x));
    float2 sf1 = __half22float2(*reinterpret_cast<__half2*>(&su.y));
    float a0x = sf0.x, a0y = sf0.y, a0z = sf1.x, a0w = sf1.y;
    float a1x = 0.f, a1y = 0.f, a1z = 0.f, a1w = 0.f;

    int beg = __ldg(&g_offs[node]);
    int end = __ldg(&g_offs[node + 1]);
    for (int j0 = beg; j0 < end; j0 += 32) {
        int rem = end - j0;
        int n = rem < 32 ? rem : 32;
        int myidx = 0;
        if (lane < n) myidx = __ldg(&g_adj[j0 + lane]);
        int jj = 0;
#pragma unroll 4
        for (; jj + 2 <= n; jj += 2) {
            int s0 = __shfl_sync(0xFFFFFFFFu, myidx, jj);
            int s1 = __shfl_sync(0xFFFFFFFFu, myidx, jj + 1);
            uint2 u0 = __ldg(&hu[s0 * 32 + lane]);
            uint2 u1 = __ldg(&hu[s1 * 32 + lane]);
            float2 f00 = __half22float2(*reinterpret_cast<__half2*>(&u0.x));
            float2 f01 = __half22float2(*reinterpret_cast<__half2*>(&u0.y));
            float2 f10 = __half22float2(*reinterpret_cast<__half2*>(&u1.x));
            float2 f11 = __half22float2(*reinterpret_cast<__half2*>(&u1.y));
            a0x += f00.x; a1x += f10.x;
            a0y += f00.y; a1y += f10.y;
            a0z += f01.x; a1z += f11.x;
            a0w += f01.y; a1w += f11.y;
        }
        if (jj < n) {
            int s0 = __shfl_sync(0xFFFFFFFFu, myidx, jj);
            uint2 u0 = __ldg(&hu[s0 * 32 + lane]);
            float2 f00 = __half22float2(*reinterpret_cast<__half2*>(&u0.x));
            float2 f01 = __half22float2(*reinterpret_cast<__half2*>(&u0.y));
            a0x += f00.x; a0y += f00.y; a0z += f01.x; a0w += f01.y;
        }
    }

    float4 b4 = __ldg(&reinterpret_cast<const float4*>(bias)[lane]);
    float ax = (a0x + a1x) * di + b4.x;
    float ay = (a0y + a1y) * di + b4.y;
    float az = (a0z + a1z) * di + b4.z;
    float aw = (a0w + a1w) * di + b4.w;

    float s = ax + ay + az + aw;
#pragma unroll
    for (int o = 16; o > 0; o >>= 1) s += __shfl_xor_sync(0xFFFFFFFFu, s, o);
    float mu = s * (1.0f / D);
    float dx = ax - mu, dy = ay - mu, dz = az - mu, dw = aw - mu;
    float sq = dx * dx + dy * dy + dz * dz + dw * dw;
#pragma unroll
    for (int o = 16; o > 0; o >>= 1) sq += __shfl_xor_sync(0xFFFFFFFFu, sq, o);
    float rs = rsqrtf(sq * (1.0f / D) + LN_EPS);

    float4 g4 = __ldg(&reinterpret_cast<const float4*>(lng)[lane]);
    float4 p4 = __ldg(&reinterpret_cast<const float4*>(lnb)[lane]);
    float4 o4;
    o4.x = fmaxf(dx * rs * g4.x + p4.x, 0.f);
    o4.y = fmaxf(dy * rs * g4.y + p4.y, 0.f);
    o4.z = fmaxf(dz * rs * g4.z + p4.z, 0.f);
    o4.w = fmaxf(dw * rs * g4.w + p4.w, 0.f);
    return o4;
}

// gather1: writes fp16 rows (consumed by k_gemmh)
__global__ void __launch_bounds__(256) k_gather1(const __half* __restrict__ h,
                                                 const float* __restrict__ bias,
                                                 const float* __restrict__ lng,
                                                 const float* __restrict__ lnb,
                                                 __half* __restrict__ outh) {
    int node = blockIdx.x * 8 + (threadIdx.x >> 5);
    if (node >= N_NODES) return;
    int lane = threadIdx.x & 31;
    float4 o4 = gather_ln_row(h, bias, lng, lnb, node, lane);
    __half2 h0 = __floats2half2_rn(o4.x, o4.y);
    __half2 h1 = __floats2half2_rn(o4.z, o4.w);
    uint2 wv;
    wv.x = *reinterpret_cast<uint32_t*>(&h0);
    wv.y = *reinterpret_cast<uint32_t*>(&h1);
    reinterpret_cast<uint2*>(outh)[node * 32 + lane] = wv;
}

// gather2: accumulates directly into g_pooled/g_gcnt (batch sorted).
// Grid is exactly N_NODES/8 blocks (100000 = 12500*8) -> no tail.
__global__ void __launch_bounds__(256) k_gather2_pool(const __half* __restrict__ h,
                                                      const float* __restrict__ bias,
                                                      const float* __restrict__ lng,
                                                      const float* __restrict__ lnb,
                                                      const int* __restrict__ batch) {
    __shared__ float acc[D];
    __shared__ int scnt;
    int tid = threadIdx.x;
    int node = blockIdx.x * 8 + (tid >> 5);
    int lane = tid & 31;

    if (tid < D) acc[tid] = 0.f;
    if (tid == 0) scnt = 0;
    __syncthreads();

    float4 o4 = gather_ln_row(h, bias, lng, lnb, node, lane);

    int gFirst = __ldg(&batch[blockIdx.x * 8]);
    int gMine  = __ldg(&batch[node]);
    if (gMine == gFirst) {
        atomicAdd(&acc[lane * 4 + 0], o4.x);
        atomicAdd(&acc[lane * 4 + 1], o4.y);
        atomicAdd(&acc[lane * 4 + 2], o4.z);
        atomicAdd(&acc[lane * 4 + 3], o4.w);
        if (lane == 0) atomicAdd(&scnt, 1);
    } else {
        atomicAdd(&g_pooled[gMine * D + lane * 4 + 0], o4.x);
        atomicAdd(&g_pooled[gMine * D + lane * 4 + 1], o4.y);
        atomicAdd(&g_pooled[gMine * D + lane * 4 + 2], o4.z);
        atomicAdd(&g_pooled[gMine * D + lane * 4 + 3], o4.w);
        if (lane == 0) atomicAdd(&g_gcnt[gMine], 1.0f);
    }
    __syncthreads();

    if (tid < D) atomicAdd(&g_pooled[gFirst * D + tid], acc[tid]);
    if (tid == 0) atomicAdd(&g_gcnt[gFirst], (float)scnt);
}

// ---------------- head ----------------
__global__ void __launch_bounds__(1024) k_final(const float* __restrict__ lw,
                                                const float* __restrict__ lb,
                                                float* __restrict__ out) {
    int t = threadIdx.x;
    int g = t >> 4;
    int o = t & 15;
    float acc = 0.f;
#pragma unroll 8
    for (int f = 0; f < D; f++) acc += g_pooled[g * D + f] * __ldg(&lw[f * DOUT + o]);
    out[t] = acc / fmaxf(g_gcnt[g], 1.0f) + __ldg(&lb[o]);
}

// ---------------- launch ----------------
extern "C" void kernel_launch(void* const* d_in, const int* in_sizes, int n_in,
                              void* d_out, int out_size) {
    const float* x     = (const float*)d_in[0];
    const int*   ei    = (const int*)d_in[1];
    const int*   src   = ei;
    const int*   dst   = ei + N_EDGES;
    const int*   batch = (const int*)d_in[2];
    const float* W1    = (const float*)d_in[3];
    const float* b1    = (const float*)d_in[4];
    const float* W2    = (const float*)d_in[5];
    const float* b2    = (const float*)d_in[6];
    const float* lng   = (const float*)d_in[7];
    const float* lnb   = (const float*)d_in[8];
    const float* lw    = (const float*)d_in[9];
    const float* lbias = (const float*)d_in[10];
    float* out = (float*)d_out;

    __half* pAh = nullptr;
    float*  pB  = nullptr;
    cudaGetSymbolAddress((void**)&pAh, g_Ah);
    cudaGetSymbolAddress((void**)&pB, g_B);
    __half* pBh = (__half*)pB;

    static cudaStream_t s_side = nullptr;
    static cudaEvent_t  s_evFork = nullptr, s_evG1 = nullptr, s_evJoin = nullptr;
    if (!s_side) {
        cudaStreamCreateWithFlags(&s_side, cudaStreamNonBlocking);
        cudaEventCreateWithFlags(&s_evFork, cudaEventDisableTiming);
        cudaEventCreateWithFlags(&s_evG1, cudaEventDisableTiming);
        cudaEventCreateWithFlags(&s_evJoin, cudaEventDisableTiming);
    }
    cudaStream_t s0 = 0;

    const int T = 256;
    // count (cnti was zeroed by the previous launch's k_zero / module init)
    k_count<<<(N_EDGES + T - 1) / T, T, 0, s0>>>(dst);

    // fork: side stream builds CSR (+ g_dinv in scan1) while main runs GEMM1
    cudaEventRecord(s_evFork, s0);
    cudaStreamWaitEvent(s_side, s_evFork, 0);
    k_scan1<<<SCAN_NB, SCAN_B, 0, s_side>>>();
    k_scan2<<<1, 128, 0, s_side>>>();
    k_scan3<<<SCAN_NB, SCAN_B, 0, s_side>>>();
    k_fill<<<(N_EDGES + T - 1) / T, T, 0, s_side>>>(src, dst);

    // GEMM1 on main stream (epilogue computes dinv from cnti)
    k_gemm<<<(N_NODES + 127) / 128, 256, 0, s0>>>(x, W1, pAh);
    cudaEventRecord(s_evG1, s0);

    // side: after gemm1's last cnti read, zero cnti/pooled/gcnt for this+next call
    cudaStreamWaitEvent(s_side, s_evG1, 0);
    k_zero<<<(N_NODES + T - 1) / T, T, 0, s_side>>>();
    cudaEventRecord(s_evJoin, s_side);

    // join: gather1 needs CSR + g_dinv; gather2 needs zeroed pooled/gcnt
    cudaStreamWaitEvent(s0, s_evJoin, 0);
    k_gather1<<<(N_NODES + 7) / 8, 256, 0, s0>>>(pAh, b1, lng, lnb, pBh);

    // layer 2
    k_gemmh<<<(N_NODES + 127) / 128, 256, 0, s0>>>(pBh, W2, pAh);
    k_gather2_pool<<<(N_NODES + 7) / 8, 256, 0, s0>>>(pAh, b2, lng, lnb, batch);

    // head
    k_final<<<1, 1024, 0, s0>>>(lw, lbias, out);
}